// round 5
// baseline (speedup 1.0000x reference)
#include <cuda_runtime.h>

// NaiveFourierKANLayer: y[b,j] = sum_{i,k} cos(x[b,i]*k)*C0[j,i,k] + sin(x[b,i]*k)*C1[j,i,k] + bias[j]
// N=2048, I=256, J=256, K=300 (k = 1..300)
//
// Strategy: SGEMM with generated A operand (cos/sin features), packed f32x2 FMA
// (sm_100+ FFMA2), 128x128 output tile, 8x8 thread tile, double-buffered smem,
// split-K over the I dimension with atomicAdd accumulation into bias-initialized out.

#define BM 128
#define BN 128
#define KC 8          // k's per smem stage
#define IC 8          // i's per CTA
#define NSPLIT 32     // 256 / IC
#define KTILES 38     // ceil(300/8); last stage has 4 valid k's
#define IDIM 256
#define JDIM 256
#define KGRID 300
#define NTHREADS 256

__device__ __forceinline__ void ffma2(unsigned long long &d,
                                      unsigned long long a,
                                      unsigned long long b) {
    // packed 2x fp32 FMA (sm_100+): d = a*b + d elementwise on (lo,hi)
    asm("fma.rn.f32x2 %0, %1, %2, %0;" : "+l"(d) : "l"(a), "l"(b));
}

__device__ __forceinline__ unsigned long long dup2(float v) {
    unsigned long long r;
    asm("mov.b64 %0, {%1, %1};" : "=l"(r) : "f"(v));
    return r;
}

__global__ void __launch_bounds__(NTHREADS)
fkan_init(float* __restrict__ out, const float* __restrict__ bias, int n) {
    int t = blockIdx.x * blockDim.x + threadIdx.x;
    if (t < n) out[t] = bias[t & (JDIM - 1)];
}

__global__ void __launch_bounds__(NTHREADS, 2)
fkan_gemm(const float* __restrict__ x,
          const float* __restrict__ coeffs,
          float* __restrict__ out)
{
    // smem: [buf][plane][k][row]; planes: F: 0=cos 1=sin ; G: 0=C0 1=C1
    __shared__ __align__(16) float Fsh[2][2][KC][BM];   // 16 KB
    __shared__ __align__(16) float Gsh[2][2][KC][BN];   // 16 KB

    const int t  = threadIdx.x;
    const int tx = t & 15;        // output row group
    const int ty = t >> 4;        // output col group
    const int b0 = blockIdx.x * BM;
    const int j0 = blockIdx.y * BN;
    const int ibase = blockIdx.z * IC;

    // coeff loader mapping: thread owns one (d, j) row, loads 8 k's per stage
    const int ld_d = t >> 7;      // 0 -> C0 (cos), 1 -> C1 (sin)
    const int ld_j = t & 127;
    const float* cbase = coeffs
        + ((size_t)(ld_d * JDIM + j0 + ld_j) * IDIM + ibase) * (size_t)KGRID;

    // feature mapping: thread owns one b-row, computes 4 k's per stage
    const int f_b  = t & 127;
    const int f_kg = (t >> 7) * 4;   // kk base within stage: 0 or 4
    const float* xrow = x + (size_t)(b0 + f_b) * IDIM + ibase;

    unsigned long long acc[8][4];    // [row][jpair] : each u64 = (y_j, y_{j+1})
    #pragma unroll
    for (int i = 0; i < 8; i++)
        #pragma unroll
        for (int j = 0; j < 4; j++) acc[i][j] = 0ULL;

    float4 rA, rB;                   // staged coeff regs for the next stage
    float  xv = xrow[0];
    int    cur_ii = 0;

    // ---- prologue: fill stage 0 directly, preload stage 1 into regs ----
    {
        float4 a = *(const float4*)cbase;          // ii=0, kb=0, k 0..3
        float4 b = *(const float4*)(cbase + 4);    // k 4..7 (kb=0 < 37, valid)
        float va[8] = {a.x, a.y, a.z, a.w, b.x, b.y, b.z, b.w};
        #pragma unroll
        for (int c = 0; c < 8; c++) Gsh[0][ld_d][c][ld_j] = va[c];
        #pragma unroll
        for (int c = 0; c < 4; c++) {
            float kf = (float)(f_kg + c + 1);
            float sn, cs;
            __sincosf(xv * kf, &sn, &cs);          // fp32 x*k matches reference rounding
            Fsh[0][0][f_kg + c][f_b] = cs;
            Fsh[0][1][f_kg + c][f_b] = sn;
        }
        const float* p1 = cbase + KC;              // ii=0, kb=1
        rA = *(const float4*)p1;
        rB = *(const float4*)(p1 + 4);
    }
    __syncthreads();

    int fi = 0, fk = 1;   // (ii,kb) of stage currently held in regs
    int li = 0, lk = 2;   // (ii,kb) of next stage to load

    const int S = IC * KTILES;   // 304 stages

    for (int s = 0; s < S; s++) {
        const int p = s & 1;

        // ---- GEMM on buffer p: 8 k-steps ----
        #pragma unroll
        for (int kk = 0; kk < KC; kk++) {
            // A frags: rows {tx*4+0..3} and {64+tx*4+0..3}  (conflict-free LDS.128)
            float4 c0 = *(const float4*)&Fsh[p][0][kk][tx * 4];
            float4 c1 = *(const float4*)&Fsh[p][0][kk][64 + tx * 4];
            float4 s0 = *(const float4*)&Fsh[p][1][kk][tx * 4];
            float4 s1 = *(const float4*)&Fsh[p][1][kk][64 + tx * 4];
            // B frags: col pairs {ty*4..+3} and {64+ty*4..+3} as packed f32x2
            ulonglong2 g0a = *(const ulonglong2*)&Gsh[p][0][kk][ty * 4];
            ulonglong2 g0b = *(const ulonglong2*)&Gsh[p][0][kk][64 + ty * 4];
            ulonglong2 g1a = *(const ulonglong2*)&Gsh[p][1][kk][ty * 4];
            ulonglong2 g1b = *(const ulonglong2*)&Gsh[p][1][kk][64 + ty * 4];
            unsigned long long cp[4] = {g0a.x, g0a.y, g0b.x, g0b.y};
            unsigned long long sp[4] = {g1a.x, g1a.y, g1b.x, g1b.y};
            float cA[8] = {c0.x, c0.y, c0.z, c0.w, c1.x, c1.y, c1.z, c1.w};
            float sA[8] = {s0.x, s0.y, s0.z, s0.w, s1.x, s1.y, s1.z, s1.w};
            #pragma unroll
            for (int bI = 0; bI < 8; bI++) {
                unsigned long long cd = dup2(cA[bI]);
                unsigned long long sd = dup2(sA[bI]);
                #pragma unroll
                for (int jp = 0; jp < 4; jp++) {
                    ffma2(acc[bI][jp], cd, cp[jp]);   // cos * C0
                    ffma2(acc[bI][jp], sd, sp[jp]);   // sin * C1
                }
            }
        }

        if (s + 1 < S) {
            const int q = p ^ 1;
            // ---- fill stage (fi, fk) into buffer q from staged regs ----
            {
                float va[8] = {rA.x, rA.y, rA.z, rA.w, rB.x, rB.y, rB.z, rB.w};
                #pragma unroll
                for (int c = 0; c < 8; c++) Gsh[q][ld_d][c][ld_j] = va[c];
                if (fi != cur_ii) { xv = xrow[fi]; cur_ii = fi; }
                const float kbase = (float)(fk * KC + f_kg + 1);
                #pragma unroll
                for (int c = 0; c < 4; c++) {
                    float sn, cs;
                    __sincosf(xv * (kbase + (float)c), &sn, &cs);
                    Fsh[q][0][f_kg + c][f_b] = cs;
                    Fsh[q][1][f_kg + c][f_b] = sn;
                }
                fk++; if (fk == KTILES) { fk = 0; fi++; }
            }
            // ---- preload stage (li, lk) into regs (zero-fill k >= 300) ----
            if (s + 2 < S) {
                const float* pp = cbase + (size_t)li * KGRID + lk * KC;
                rA = *(const float4*)pp;
                if (lk < KTILES - 1) rB = *(const float4*)(pp + 4);
                else                 rB = make_float4(0.f, 0.f, 0.f, 0.f);
                lk++; if (lk == KTILES) { lk = 0; li++; }
            }
        }
        __syncthreads();
    }

    // ---- epilogue: split-K accumulate via fp32 REDG ----
    #pragma unroll
    for (int bI = 0; bI < 8; bI++) {
        int row = b0 + ((bI < 4) ? (tx * 4 + bI) : (64 + tx * 4 + bI - 4));
        float* orow = out + (size_t)row * JDIM + j0;
        #pragma unroll
        for (int jp = 0; jp < 4; jp++) {
            int col = (jp < 2) ? (ty * 4 + 2 * jp) : (64 + ty * 4 + 2 * (jp - 2));
            float lo, hi;
            asm("mov.b64 {%0, %1}, %2;" : "=f"(lo), "=f"(hi) : "l"(acc[bI][jp]));
            atomicAdd(orow + col,     lo);
            atomicAdd(orow + col + 1, hi);
        }
    }
}

extern "C" void kernel_launch(void* const* d_in, const int* in_sizes, int n_in,
                              void* d_out, int out_size)
{
    const float* x      = (const float*)d_in[0];   // [2048, 256]
    const float* coeffs = (const float*)d_in[1];   // [2, 256, 256, 300]
    const float* bias   = (const float*)d_in[2];   // [1, 256]
    float* out = (float*)d_out;                    // [2048, 256] fp32

    fkan_init<<<(out_size + NTHREADS - 1) / NTHREADS, NTHREADS>>>(out, bias, out_size);

    dim3 grid(2048 / BM, JDIM / BN, NSPLIT);       // (16, 2, 32) = 1024 CTAs
    fkan_gemm<<<grid, NTHREADS>>>(x, coeffs, out);
}

// round 7
// speedup vs baseline: 2.7945x; 2.7945x over previous
#include <cuda_runtime.h>
#include <cstdint>

// NaiveFourierKANLayer via mma.sync tf32 (portable HMMA path; tcgen05 is
// unavailable because the harness ptxas target is sm_103 without the 'a').
// y[b,j] = sum_{i,k} cos(x[b,i]k)C0[j,i,k] + sin(x[b,i]k)C1[j,i,k] + bias[j]
// GEMM: M=2048(b), N=256(j), K = (i, plane, k) = 153600 (k padded 300->304).

#define NT     256
#define BMT    128          // CTA M tile
#define ID     256
#define JD     256
#define KG     300
#define SPLIT  8
#define I_PER  32           // i's per CTA
#define KCPI   19           // 16-angle chunks per i (19*16 = 304 >= 300)
#define STAGES (I_PER * KCPI)   // 608

#define CTRL   1024
#define A_SZ   16384        // 128 rows x 128B  ([cos16|sin16] tf32)
#define B_SZ   32768        // 256 rows x 128B  ([C0 k16 | C1 k16] tf32)
#define STG    (A_SZ + B_SZ)
#define SMEM_TOTAL (CTRL + 3 * STG)   // 148480

// tf32-RNA-rounded, SW128-pre-swizzled coeff tiles, k padded to 304:
// tile (i*19+kc): [256 j rows][8 chunks of 16B], chunk c<4 = C0, c>=4 = C1.
__device__ __align__(128) float g_B[(size_t)ID * KCPI * JD * 32];

__device__ __forceinline__ uint32_t s2u(const void* p) {
    uint32_t a;
    asm("{ .reg .u64 t; cvta.to.shared.u64 t, %1; cvt.u32.u64 %0, t; }" : "=r"(a) : "l"(p));
    return a;
}
__device__ __forceinline__ float tf32rn(float x) {
    uint32_t o; asm("cvt.rna.satfinite.tf32.f32 %0, %1;" : "=r"(o) : "f"(x));
    return __uint_as_float(o);
}

#define MBAR_INIT(a, c) asm volatile("mbarrier.init.shared.b64 [%0], %1;" :: "r"(a), "r"(c) : "memory")
#define MBAR_ARRIVE(a)  asm volatile("mbarrier.arrive.shared.b64 _, [%0];" :: "r"(a) : "memory")
#define MBAR_EXPECT_TX(a, b) \
    asm volatile("mbarrier.arrive.expect_tx.shared.b64 _, [%0], %1;" :: "r"(a), "r"(b) : "memory")
#define MBAR_WAIT(a, ph)                                                              \
    asm volatile("{\n\t.reg .pred P;\n\t"                                             \
        "WL_%=:\n\t"                                                                  \
        "mbarrier.try_wait.parity.acquire.cta.shared::cta.b64 P, [%0], %1, 0x989680;\n\t" \
        "@P bra.uni WD_%=;\n\t"                                                       \
        "bra.uni WL_%=;\n\t"                                                          \
        "WD_%=:\n\t}" :: "r"(a), "r"(ph) : "memory")

#define LDSM4(R, addr)                                                                \
    asm volatile("ldmatrix.sync.aligned.m8n8.x4.shared.b16 {%0,%1,%2,%3}, [%4];"      \
        : "=r"((R)[0]), "=r"((R)[1]), "=r"((R)[2]), "=r"((R)[3]) : "r"(addr))

__device__ __forceinline__ void mma8(float* d, const uint32_t* a, const uint32_t* b) {
    asm volatile("mma.sync.aligned.m16n8k8.row.col.f32.tf32.tf32.f32 "
        "{%0,%1,%2,%3}, {%4,%5,%6,%7}, {%8,%9}, {%0,%1,%2,%3};"
        : "+f"(d[0]), "+f"(d[1]), "+f"(d[2]), "+f"(d[3])
        : "r"(a[0]), "r"(a[1]), "r"(a[2]), "r"(a[3]), "r"(b[0]), "r"(b[1]));
}

// ---------------------------------------------------------------------------
__global__ void __launch_bounds__(NT)
fkan_init(float* __restrict__ out, const float* __restrict__ bias, int n) {
    int t = blockIdx.x * blockDim.x + threadIdx.x;
    if (t < n) out[t] = bias[t & (JD - 1)];
}

// coeffs[d][j][i][k] -> g_B, tf32 RNA-rounded, SW128-swizzled, k padded.
__global__ void __launch_bounds__(NT)
fkan_pre(const float* __restrict__ co) {
    size_t lin = (size_t)blockIdx.x * NT + threadIdx.x;   // ((i*19+kc)*256+j)*8+c
    if (lin >= (size_t)ID * KCPI * JD * 8) return;
    int c    = (int)(lin & 7);
    int j    = (int)((lin >> 3) & 255);
    int tile = (int)(lin >> 11);
    int kc   = tile % KCPI;
    int i    = tile / KCPI;
    int d    = c >> 2;
    int k    = kc * 16 + (c & 3) * 4;

    float4 v = make_float4(0.f, 0.f, 0.f, 0.f);
    if (k < KG) {  // k <= 296 here, so k..k+3 stays inside the 300-long row
        v = *(const float4*)(co + ((size_t)(d * JD + j) * ID + i) * KG + k);
        v.x = tf32rn(v.x); v.y = tf32rn(v.y); v.z = tf32rn(v.z); v.w = tf32rn(v.w);
    }
    uint32_t off = (uint32_t)j * 128 + (((uint32_t)c ^ (uint32_t)(j & 7)) << 4);
    *(float4*)((char*)g_B + (size_t)tile * 32768 + off) = v;
}

// ---------------------------------------------------------------------------
struct PState { float xv, c2, s2; };

__device__ __forceinline__ void produce(int u, uint32_t sb, char* smem, int ibase,
                                        const float* xp, int t, int r, int h, PState& P)
{
    const int slot = u % 3;
    const int kc   = u % KCPI;
    const int il   = u / KCPI;
    const uint32_t mF = sb + (uint32_t)slot * 8u;

    if (t == 0) {   // B: one 32KB pre-swizzled bulk copy
        const char* src = (const char*)g_B + (size_t)((ibase + il) * KCPI + kc) * 32768;
        MBAR_EXPECT_TX(mF, (uint32_t)B_SZ);
        asm volatile("cp.async.bulk.shared::cluster.global.mbarrier::complete_tx::bytes "
                     "[%0], [%1], %2, [%3];"
                     :: "r"(sb + CTRL + slot * STG + A_SZ), "l"(src),
                        "r"((uint32_t)B_SZ), "r"(mF) : "memory");
    }

    if (kc == 0) { P.xv = xp[il]; __sincosf(P.xv + P.xv, &P.s2, &P.c2); }

    // 16 angles k = kc*16 + {1..16}: 2 MUFU seeds + rotations by 2x.
    const float k0f = (float)(kc * 16 + 1);
    float s0, c0, s1, c1;
    __sincosf(P.xv * k0f,          &s0, &c0);   // fp32 x*k matches reference rounding
    __sincosf(P.xv * (k0f + 1.f),  &s1, &c1);

    char* Arow = smem + CTRL + slot * STG + r * 128;
    const uint32_t msk = (uint32_t)(r & 7);
    #pragma unroll
    for (int q = 0; q < 4; q++) {
        float v0 = h ? s0 : c0;
        float v1 = h ? s1 : c1;
        float nc0 = c0 * P.c2 - s0 * P.s2, ns0 = s0 * P.c2 + c0 * P.s2;
        float nc1 = c1 * P.c2 - s1 * P.s2, ns1 = s1 * P.c2 + c1 * P.s2;
        float v2 = h ? ns0 : nc0;
        float v3 = h ? ns1 : nc1;
        c0 = nc0 * P.c2 - ns0 * P.s2;  s0 = ns0 * P.c2 + nc0 * P.s2;
        c1 = nc1 * P.c2 - ns1 * P.s2;  s1 = ns1 * P.c2 + nc1 * P.s2;
        float4 w;
        w.x = tf32rn(v0); w.y = tf32rn(v1); w.z = tf32rn(v2); w.w = tf32rn(v3);
        if (kc == KCPI - 1 && q == 3) w = make_float4(0.f, 0.f, 0.f, 0.f);  // k > 300
        *(float4*)(Arow + ((((uint32_t)(h * 4 + q)) ^ msk) << 4)) = w;
    }
    MBAR_ARRIVE(mF);   // release: A stores visible to full-waiters
}

__global__ void __launch_bounds__(NT, 1)
fkan_gemm(const float* __restrict__ x, float* __restrict__ out)
{
    extern __shared__ char smem[];
    const uint32_t sb = s2u(smem);
    const int t = threadIdx.x, lane = t & 31, wid = t >> 5;
    const int b0    = blockIdx.x * BMT;
    const int ibase = blockIdx.y * I_PER;

    if (t == 0) { MBAR_INIT(sb, 257); MBAR_INIT(sb + 8, 257); MBAR_INIT(sb + 16, 257); }
    __syncthreads();

    // producer ids: r = m-row, h = plane half (0=cos chunks 0-3, 1=sin chunks 4-7)
    const int r = t & 127, h = t >> 7;
    const float* xp = x + (size_t)(b0 + r) * ID + ibase;
    PState P;

    // consumer: 8 warps as 2(m) x 4(n), warp tile 64x64
    const int wm = wid >> 2, wn = wid & 3;
    const int mbase = wm * 64, nbase = wn * 64;
    const uint32_t msk = (uint32_t)(lane & 7);
    const int a_rl = ((lane >> 3) & 1) * 8 + (lane & 7);       // ldmatrix A row-in-group
    const uint32_t akh = (uint32_t)(lane >> 4);                // A k-half
    const int b_rl = ((lane >> 4) << 3) + (lane & 7);          // ldmatrix B row-in-group
    const uint32_t bkh = (uint32_t)((lane >> 3) & 1);          // B k-half
    uint32_t aoff[4], boff[4];
    #pragma unroll
    for (int mi = 0; mi < 4; mi++) aoff[mi] = (uint32_t)(mbase + mi * 16 + a_rl) * 128u;
    #pragma unroll
    for (int g = 0; g < 4; g++)   boff[g] = (uint32_t)(nbase + g * 16 + b_rl) * 128u;

    float acc[4][8][4];
    #pragma unroll
    for (int a = 0; a < 4; a++)
        #pragma unroll
        for (int b = 0; b < 8; b++)
            #pragma unroll
            for (int c = 0; c < 4; c++) acc[a][b][c] = 0.f;

    produce(0, sb, smem, ibase, xp, t, r, h, P);
    produce(1, sb, smem, ibase, xp, t, r, h, P);
    produce(2, sb, smem, ibase, xp, t, r, h, P);

    for (int s = 0; s < STAGES; s++) {
        const int slot = s % 3;
        const uint32_t ph = (uint32_t)((s / 3) & 1);
        MBAR_WAIT(sb + (uint32_t)slot * 8u, ph);
        const uint32_t Ab = sb + CTRL + slot * STG;
        const uint32_t Bb = Ab + A_SZ;
        #pragma unroll
        for (int kq = 0; kq < 4; kq++) {
            uint32_t av[4][4], bv[4][4];
            const uint32_t ak = ((((uint32_t)(kq * 2) + akh) ^ msk) << 4);
            const uint32_t bk = ((((uint32_t)(kq * 2) + bkh) ^ msk) << 4);
            #pragma unroll
            for (int mi = 0; mi < 4; mi++) LDSM4(av[mi], Ab + aoff[mi] + ak);
            #pragma unroll
            for (int g = 0; g < 4; g++)   LDSM4(bv[g], Bb + boff[g] + bk);
            #pragma unroll
            for (int mi = 0; mi < 4; mi++)
                #pragma unroll
                for (int nt = 0; nt < 8; nt++)
                    mma8(acc[mi][nt], av[mi], &bv[nt >> 1][(nt & 1) * 2]);
        }
        if (s + 3 < STAGES) {
            __syncthreads();                      // all readers done with this slot
            produce(s + 3, sb, smem, ibase, xp, t, r, h, P);
        }
    }

    // epilogue: split-K accumulate (out pre-initialized with bias)
    const int g4 = lane >> 2, t4 = lane & 3;
    #pragma unroll
    for (int mi = 0; mi < 4; mi++) {
        const int row = b0 + mbase + mi * 16 + g4;
        #pragma unroll
        for (int nt = 0; nt < 8; nt++) {
            const int col = nbase + nt * 8 + t4 * 2;
            atomicAdd(out + (size_t)row * JD + col,           acc[mi][nt][0]);
            atomicAdd(out + (size_t)row * JD + col + 1,       acc[mi][nt][1]);
            atomicAdd(out + (size_t)(row + 8) * JD + col,     acc[mi][nt][2]);
            atomicAdd(out + (size_t)(row + 8) * JD + col + 1, acc[mi][nt][3]);
        }
    }
}

// ---------------------------------------------------------------------------
extern "C" void kernel_launch(void* const* d_in, const int* in_sizes, int n_in,
                              void* d_out, int out_size)
{
    const float* x    = (const float*)d_in[0];   // [2048, 256]
    const float* co   = (const float*)d_in[1];   // [2, 256, 256, 300]
    const float* bias = (const float*)d_in[2];   // [1, 256]
    float* out = (float*)d_out;                  // [2048, 256] fp32

    cudaFuncSetAttribute(fkan_gemm, cudaFuncAttributeMaxDynamicSharedMemorySize, SMEM_TOTAL);

    fkan_init<<<(out_size + NT - 1) / NT, NT>>>(out, bias, out_size);
    fkan_pre<<<(int)(((size_t)ID * KCPI * JD * 8 + NT - 1) / NT), NT>>>(co);

    dim3 grid(2048 / BMT, SPLIT);                // (16, 8) = 128 CTAs, one wave
    fkan_gemm<<<grid, NT, SMEM_TOTAL>>>(x, out);
}